// round 9
// baseline (speedup 1.0000x reference)
#include <cuda_runtime.h>

#define EPS 0.001f
typedef unsigned long long u64;

// ---- packed f32x2 helpers (sm_100+) ----
__device__ __forceinline__ u64 pk2(float lo, float hi) {
    u64 r; asm("mov.b64 %0,{%1,%2};" : "=l"(r) : "f"(lo), "f"(hi)); return r;
}
__device__ __forceinline__ void upk2(u64 v, float& lo, float& hi) {
    asm("mov.b64 {%0,%1},%2;" : "=f"(lo), "=f"(hi) : "l"(v));
}
__device__ __forceinline__ u64 ffma2(u64 a, u64 b, u64 c) {
    u64 d; asm("fma.rn.f32x2 %0,%1,%2,%3;" : "=l"(d) : "l"(a), "l"(b), "l"(c)); return d;
}
__device__ __forceinline__ u64 fmul2(u64 a, u64 b) {
    u64 d; asm("mul.rn.f32x2 %0,%1,%2;" : "=l"(d) : "l"(a), "l"(b)); return d;
}

// Table: 64 mask entries, 9 x u64 stride (72B; even -> 8B aligned LDS.64,
// gcd(18,32)=2 -> <=2-way bank conflicts). 8 u64 used per entry:
//  [0]=(S00,S10) [1]=(S01,S11) [2]=(sb0,sb1) [3]=(E0,E1)
//  [4]=(lb,0)    [5]=(G00,G10) [6]=(G01,G11) [7]=(gb0,gb1)
#define TSU 9

struct W1p { u64 c0[3], c1[3], bp[3]; };  // W1 columns / b1, packed over j-pairs

__device__ __forceinline__ void compute_row(
    float q0, float q1, float qd0, float qd1, float qdd0, float qdd1,
    const W1p& w, const u64* __restrict__ tab, float& t0, float& t1)
{
    const u64 q0p = pk2(q0, q0), q1p = pk2(q1, q1);

    // z = W1 q + b1 (packed over j-pairs), ReLU mask via sign-bit trick
    float z0, z1, z2, z3, z4, z5;
    upk2(ffma2(w.c0[0], q0p, ffma2(w.c1[0], q1p, w.bp[0])), z0, z1);
    upk2(ffma2(w.c0[1], q0p, ffma2(w.c1[1], q1p, w.bp[1])), z2, z3);
    upk2(ffma2(w.c0[2], q0p, ffma2(w.c1[2], q1p, w.bp[2])), z4, z5);

    int mask =  (int)((~__float_as_uint(z0)) >> 31)
             | ((int)((~__float_as_uint(z1)) >> 31) << 1)
             | ((int)((~__float_as_uint(z2)) >> 31) << 2)
             | ((int)((~__float_as_uint(z3)) >> 31) << 3)
             | ((int)((~__float_as_uint(z4)) >> 31) << 4)
             | ((int)((~__float_as_uint(z5)) >> 31) << 5);

    // 8 x LDS.64 lookup
    const u64* e = tab + mask * TSU;
    const u64 Sc0 = e[0], Sc1 = e[1], sbp = e[2], Ep = e[3];
    const u64 lbp = e[4], Gc0 = e[5], Gc1 = e[6], gbp = e[7];

    // s3 = S q + sb ; g = G q + gb  (packed over output component)
    const u64 s3p = ffma2(Sc0, q0p, ffma2(Sc1, q1p, sbp));
    const u64 gp  = ffma2(Gc0, q0p, ffma2(Gc1, q1p, gbp));

    float E0, E1; upk2(Ep, E0, E1);
    float lb, lbpad; upk2(lbp, lb, lbpad); (void)lbpad;
    const float c = fmaf(E0, q0, fmaf(E1, q1, lb));   // lo

    float s30, s31; upk2(s3p, s30, s31);
    float g0, g1;   upk2(gp, g0, g1);

    const float a = fmaxf(s30, 0.0f);
    const float b = fmaxf(s31, 0.0f);
    const float m0 = (s30 > 0.0f) ? 1.0f : 0.0f;
    const float m1 = (s31 > 0.0f) ? 1.0f : 0.0f;
    const u64 mp = pk2(m0, m1);

    // d columns (masked Jacobian): (d00,d10), (d01,d11)
    const u64 dc0 = fmul2(Sc0, mp);
    const u64 dc1 = fmul2(Sc1, mp);

    const u64 qd0p = pk2(qd0, qd0), qd1p = pk2(qd1, qd1);
    // (da, db) = d[:,0]*qd0 + d[:,1]*qd1
    const u64 dadb = ffma2(dc0, qd0p, fmul2(dc1, qd1p));

    float da, db;   upk2(dadb, da, db);
    float d00, d10; upk2(dc0, d00, d10);
    float d01, d11; upk2(dc1, d01, d11);
    const float dcv = fmaf(E0, qd0, E1 * qd1);   // dlo_dt

    // H q_ddot = L^T (L q_ddot) + eps q_ddot,  L = [[a,0],[c,b]]
    const float Lq0 = a * qdd0;
    const float Lq1 = fmaf(c, qdd0, b * qdd1);
    const float Hq0 = fmaf(a, Lq0, fmaf(c, Lq1, EPS * qdd0));
    const float Hq1 = fmaf(b, Lq1, EPS * qdd1);

    // dH_dt terms
    const float dh01 = fmaf(a, dcv, c * da);
    const float dHq0 = fmaf(2.0f * a * da, qd0, dh01 * qd1);
    const float dHq1 = fmaf(dh01, qd0, 2.0f * fmaf(c, dcv, b * db) * qd1);

    // quad_i = 2 (B_i^T qd) . (L^T qd)
    const float Ltq0 = fmaf(a, qd0, c * qd1);
    const float Ltq1 = b * qd1;
    const float quad0 = 2.0f * fmaf(fmaf(d00, qd0, E0 * qd1), Ltq0, d10 * qd1 * Ltq1);
    const float quad1 = 2.0f * fmaf(fmaf(d01, qd0, E1 * qd1), Ltq0, d11 * qd1 * Ltq1);

    t0 = Hq0 + dHq0 + quad0 + g0;
    t1 = Hq1 + dHq1 + quad1 + g1;
}

__global__ void __launch_bounds__(128, 7)
lnn_tau_kernel(const float* __restrict__ x,
               const float* __restrict__ W1, const float* __restrict__ b1,
               const float* __restrict__ W2, const float* __restrict__ b2,
               const float* __restrict__ W3, const float* __restrict__ b3,
               const float* __restrict__ W4, const float* __restrict__ b4,
               float* __restrict__ out, int n)
{
    __shared__ __align__(8) float tab[64 * TSU * 2];

    // Build the 64-entry full piecewise-linear table.
    if (threadIdx.x < 64) {
        const int m = threadIdx.x;
        float S00 = 0.f, S01 = 0.f, S10 = 0.f, S11 = 0.f;
        float sb0 = b3[0], sb1 = b3[1];
        float E0 = 0.f, E1 = 0.f, lb = b4[0];
        float G00 = 0.f, G01 = 0.f, G10 = 0.f, G11 = 0.f;
        float gb0 = b2[0], gb1 = b2[1];
#pragma unroll
        for (int j = 0; j < 6; j++) {
            if ((m >> j) & 1) {
                const float a0 = W1[2 * j], a1 = W1[2 * j + 1], bb = b1[j];
                const float w30 = W3[j], w31 = W3[6 + j];
                const float w20 = W2[j], w21 = W2[6 + j];
                const float w4j = W4[j];
                S00 = fmaf(w30, a0, S00); S01 = fmaf(w30, a1, S01); sb0 = fmaf(w30, bb, sb0);
                S10 = fmaf(w31, a0, S10); S11 = fmaf(w31, a1, S11); sb1 = fmaf(w31, bb, sb1);
                E0  = fmaf(w4j, a0, E0);  E1  = fmaf(w4j, a1, E1);  lb  = fmaf(w4j, bb, lb);
                G00 = fmaf(w20, a0, G00); G01 = fmaf(w20, a1, G01); gb0 = fmaf(w20, bb, gb0);
                G10 = fmaf(w21, a0, G10); G11 = fmaf(w21, a1, G11); gb1 = fmaf(w21, bb, gb1);
            }
        }
        float* e = tab + m * TSU * 2;
        e[0]  = S00; e[1]  = S10;   // (S00,S10)
        e[2]  = S01; e[3]  = S11;   // (S01,S11)
        e[4]  = sb0; e[5]  = sb1;
        e[6]  = E0;  e[7]  = E1;
        e[8]  = lb;  e[9]  = 0.0f;
        e[10] = G00; e[11] = G10;
        e[12] = G01; e[13] = G11;
        e[14] = gb0; e[15] = gb1;
    }

    // Per-thread registers: only W1/b1 (for the mask planes), packed.
    W1p w;
#pragma unroll
    for (int p = 0; p < 3; p++) {
        w.c0[p] = pk2(__ldg(W1 + 4 * p),     __ldg(W1 + 4 * p + 2));
        w.c1[p] = pk2(__ldg(W1 + 4 * p + 1), __ldg(W1 + 4 * p + 3));
        w.bp[p] = pk2(__ldg(b1 + 2 * p),     __ldg(b1 + 2 * p + 1));
    }
    __syncthreads();

    const u64* tab64 = reinterpret_cast<const u64*>(tab);
    const int np = n >> 1;  // pairs of rows
    const int stride = gridDim.x * blockDim.x;

    for (int p = blockIdx.x * blockDim.x + threadIdx.x; p < np; p += stride) {
        const float4* xp = reinterpret_cast<const float4*>(x + (size_t)p * 12);
        const float4 u0 = xp[0], u1 = xp[1], u2 = xp[2];

        float o0, o1, o2, o3;
        compute_row(u0.x, u0.y, u0.z, u0.w, u1.x, u1.y, w, tab64, o0, o1);
        compute_row(u1.z, u1.w, u2.x, u2.y, u2.z, u2.w, w, tab64, o2, o3);

        reinterpret_cast<float4*>(out)[p] = make_float4(o0, o1, o2, o3);
    }

    // Tail (n odd) — n is even here; kept for safety.
    if ((n & 1) && blockIdx.x == 0 && threadIdx.x == 0) {
        const int row = n - 1;
        float t0, t1;
        compute_row(x[(size_t)row * 6 + 0], x[(size_t)row * 6 + 1],
                    x[(size_t)row * 6 + 2], x[(size_t)row * 6 + 3],
                    x[(size_t)row * 6 + 4], x[(size_t)row * 6 + 5],
                    w, tab64, t0, t1);
        out[(size_t)row * 2 + 0] = t0;
        out[(size_t)row * 2 + 1] = t1;
    }
}

extern "C" void kernel_launch(void* const* d_in, const int* in_sizes, int n_in,
                              void* d_out, int out_size)
{
    const float* x  = (const float*)d_in[0];
    const float* W1 = (const float*)d_in[1];
    const float* b1 = (const float*)d_in[2];
    const float* W2 = (const float*)d_in[3];
    const float* b2 = (const float*)d_in[4];
    const float* W3 = (const float*)d_in[5];
    const float* b3 = (const float*)d_in[6];
    const float* W4 = (const float*)d_in[7];
    const float* b4 = (const float*)d_in[8];
    float* out = (float*)d_out;

    const int n = in_sizes[0] / 6;   // rows

    // Persistent-style grid: 7 blocks/SM resident, grid-stride
    const int threads = 128;
    const int blocks = 148 * 7;
    lnn_tau_kernel<<<blocks, threads>>>(x, W1, b1, W2, b2, W3, b3, W4, b4, out, n);
}

// round 10
// speedup vs baseline: 1.1214x; 1.1214x over previous
#include <cuda_runtime.h>

#define EPS 0.001f
#define TS 15  // table stride in floats; odd -> <=2-way LDS bank conflicts

// Per-mask table entry (15 floats): full piecewise-linear form.
//  [0..3]  S00 S01 S10 S11   (pre-mask Jacobian of s3 wrt q)
//  [4..5]  sb0 sb1           (s3 = S q + sb)
//  [6..7]  E0 E1             (dlo_dq; lo = E q + lb)
//  [8]     lb
//  [9..12] G00 G01 G10 G11   (g = G q + gb)
//  [13..14] gb0 gb1

__device__ __forceinline__ void compute_row(
    float q0, float q1, float qd0, float qd1, float qdd0, float qdd1,
    const float* __restrict__ w1r, const float* __restrict__ b1r,
    const float* __restrict__ tab, float& t0, float& t1)
{
    // ReLU mask only (no h needed: everything downstream is linear per mask)
    int mask = 0;
#pragma unroll
    for (int j = 0; j < 6; j++) {
        float z = fmaf(w1r[2 * j], q0, fmaf(w1r[2 * j + 1], q1, b1r[j]));
        mask |= (int)((~__float_as_uint(z)) >> 31) << j;
    }

    // 15 scalar LDS at odd stride (<=2-way conflicts — empirically the best
    // divergent-lookup delivery on sm_103a)
    const float* e = tab + mask * TS;
    const float S00 = e[0], S01 = e[1], S10 = e[2], S11 = e[3];
    const float s30 = fmaf(S00, q0, fmaf(S01, q1, e[4]));
    const float s31 = fmaf(S10, q0, fmaf(S11, q1, e[5]));
    const float E0 = e[6], E1 = e[7];
    const float c = fmaf(E0, q0, fmaf(E1, q1, e[8]));          // lo
    const float g0 = fmaf(e[9],  q0, fmaf(e[10], q1, e[13]));
    const float g1 = fmaf(e[11], q0, fmaf(e[12], q1, e[14]));

    const float a = fmaxf(s30, 0.0f);
    const float b = fmaxf(s31, 0.0f);
    const float m0 = (s30 > 0.0f) ? 1.0f : 0.0f;
    const float m1 = (s31 > 0.0f) ? 1.0f : 0.0f;

    const float d00 = S00 * m0, d01 = S01 * m0;
    const float d10 = S10 * m1, d11 = S11 * m1;

    // time derivatives
    const float da = fmaf(d00, qd0, d01 * qd1);
    const float db = fmaf(d10, qd0, d11 * qd1);
    const float dc = fmaf(E0,  qd0, E1  * qd1);

    // H q_ddot = L^T (L q_ddot) + eps q_ddot,  L = [[a,0],[c,b]]
    const float Lq0 = a * qdd0;
    const float Lq1 = fmaf(c, qdd0, b * qdd1);
    const float Hq0 = fmaf(a, Lq0, fmaf(c, Lq1, EPS * qdd0));
    const float Hq1 = fmaf(b, Lq1, EPS * qdd1);

    // dH_dt terms
    const float dh01 = fmaf(a, dc, c * da);
    const float dHq0 = fmaf(2.0f * a * da, qd0, dh01 * qd1);
    const float dHq1 = fmaf(dh01, qd0, 2.0f * fmaf(c, dc, b * db) * qd1);

    // quad_i = 2 (B_i^T qd) . (L^T qd)
    const float Ltq0 = fmaf(a, qd0, c * qd1);
    const float Ltq1 = b * qd1;
    const float quad0 = 2.0f * fmaf(fmaf(d00, qd0, E0 * qd1), Ltq0, d10 * qd1 * Ltq1);
    const float quad1 = 2.0f * fmaf(fmaf(d01, qd0, E1 * qd1), Ltq0, d11 * qd1 * Ltq1);

    t0 = Hq0 + dHq0 + quad0 + g0;
    t1 = Hq1 + dHq1 + quad1 + g1;
}

__global__ void __launch_bounds__(128, 8)
lnn_tau_kernel(const float* __restrict__ x,
               const float* __restrict__ W1, const float* __restrict__ b1,
               const float* __restrict__ W2, const float* __restrict__ b2,
               const float* __restrict__ W3, const float* __restrict__ b3,
               const float* __restrict__ W4, const float* __restrict__ b4,
               float* __restrict__ out, int n)
{
    __shared__ float tab[64 * TS];

    // Build the 64-entry full piecewise-linear table.
    if (threadIdx.x < 64) {
        const int m = threadIdx.x;
        float S00 = 0.f, S01 = 0.f, S10 = 0.f, S11 = 0.f;
        float sb0 = b3[0], sb1 = b3[1];
        float E0 = 0.f, E1 = 0.f, lb = b4[0];
        float G00 = 0.f, G01 = 0.f, G10 = 0.f, G11 = 0.f;
        float gb0 = b2[0], gb1 = b2[1];
#pragma unroll
        for (int j = 0; j < 6; j++) {
            if ((m >> j) & 1) {
                const float a0 = W1[2 * j], a1 = W1[2 * j + 1], bb = b1[j];
                const float w30 = W3[j], w31 = W3[6 + j];
                const float w20 = W2[j], w21 = W2[6 + j];
                const float w4j = W4[j];
                S00 = fmaf(w30, a0, S00); S01 = fmaf(w30, a1, S01); sb0 = fmaf(w30, bb, sb0);
                S10 = fmaf(w31, a0, S10); S11 = fmaf(w31, a1, S11); sb1 = fmaf(w31, bb, sb1);
                E0  = fmaf(w4j, a0, E0);  E1  = fmaf(w4j, a1, E1);  lb  = fmaf(w4j, bb, lb);
                G00 = fmaf(w20, a0, G00); G01 = fmaf(w20, a1, G01); gb0 = fmaf(w20, bb, gb0);
                G10 = fmaf(w21, a0, G10); G11 = fmaf(w21, a1, G11); gb1 = fmaf(w21, bb, gb1);
            }
        }
        float* e = tab + m * TS;
        e[0] = S00;  e[1] = S01;  e[2] = S10;  e[3] = S11;
        e[4] = sb0;  e[5] = sb1;
        e[6] = E0;   e[7] = E1;   e[8] = lb;
        e[9] = G00;  e[10] = G01; e[11] = G10; e[12] = G11;
        e[13] = gb0; e[14] = gb1;
    }

    // Per-thread registers: only W1/b1 (mask planes), amortized over ~8 iters.
    float w1r[12], b1r[6];
#pragma unroll
    for (int j = 0; j < 6; j++) {
        w1r[2 * j]     = __ldg(W1 + 2 * j);
        w1r[2 * j + 1] = __ldg(W1 + 2 * j + 1);
        b1r[j]         = __ldg(b1 + j);
    }
    __syncthreads();

    const int np = n >> 1;  // pairs of rows
    const int stride = gridDim.x * blockDim.x;

    for (int p = blockIdx.x * blockDim.x + threadIdx.x; p < np; p += stride) {
        const float4* xp = reinterpret_cast<const float4*>(x + (size_t)p * 12);
        const float4 u0 = xp[0], u1 = xp[1], u2 = xp[2];

        float o0, o1, o2, o3;
        compute_row(u0.x, u0.y, u0.z, u0.w, u1.x, u1.y, w1r, b1r, tab, o0, o1);
        compute_row(u1.z, u1.w, u2.x, u2.y, u2.z, u2.w, w1r, b1r, tab, o2, o3);

        reinterpret_cast<float4*>(out)[p] = make_float4(o0, o1, o2, o3);
    }

    // Tail (n odd) — n is even here; kept for safety.
    if ((n & 1) && blockIdx.x == 0 && threadIdx.x == 0) {
        const int row = n - 1;
        float t0, t1;
        compute_row(x[(size_t)row * 6 + 0], x[(size_t)row * 6 + 1],
                    x[(size_t)row * 6 + 2], x[(size_t)row * 6 + 3],
                    x[(size_t)row * 6 + 4], x[(size_t)row * 6 + 5],
                    w1r, b1r, tab, t0, t1);
        out[(size_t)row * 2 + 0] = t0;
        out[(size_t)row * 2 + 1] = t1;
    }
}

extern "C" void kernel_launch(void* const* d_in, const int* in_sizes, int n_in,
                              void* d_out, int out_size)
{
    const float* x  = (const float*)d_in[0];
    const float* W1 = (const float*)d_in[1];
    const float* b1 = (const float*)d_in[2];
    const float* W2 = (const float*)d_in[3];
    const float* b2 = (const float*)d_in[4];
    const float* W3 = (const float*)d_in[5];
    const float* b3 = (const float*)d_in[6];
    const float* W4 = (const float*)d_in[7];
    const float* b4 = (const float*)d_in[8];
    float* out = (float*)d_out;

    const int n = in_sizes[0] / 6;   // rows

    // Persistent-style grid: 8 blocks/SM resident, grid-stride (~8 iters/thread)
    const int threads = 128;
    const int blocks = 148 * 8;
    lnn_tau_kernel<<<blocks, threads>>>(x, W1, b1, W2, b2, W3, b3, W4, b4, out, n);
}

// round 11
// speedup vs baseline: 1.2338x; 1.1002x over previous
#include <cuda_runtime.h>

#define EPS 0.001f
#define TS 9   // table stride in floats (odd -> <=2-way LDS bank conflicts)
typedef unsigned long long u64;

// ---- packed f32x2 helpers (sm_100+) ----
__device__ __forceinline__ u64 pk2(float lo, float hi) {
    u64 r; asm("mov.b64 %0,{%1,%2};" : "=l"(r) : "f"(lo), "f"(hi)); return r;
}
__device__ __forceinline__ void upk2(u64 v, float& lo, float& hi) {
    asm("mov.b64 {%0,%1},%2;" : "=f"(lo), "=f"(hi) : "l"(v));
}
__device__ __forceinline__ u64 ffma2(u64 a, u64 b, u64 c) {
    u64 d; asm("fma.rn.f32x2 %0,%1,%2,%3;" : "=l"(d) : "l"(a), "l"(b), "l"(c)); return d;
}

struct W1p { u64 c0[3], c1[3], bp[3]; };  // W1 columns / b1, packed over j-pairs

// Per-mask table entry (9 floats):
//  [0..3] S00 S01 S10 S11  (pre-mask Jacobian of s3 wrt q)
//  [4..5] sb0 sb1          (s3 = S q + sb)
//  [6..7] E0 E1            (dlo_dq; lo = E q + lb)
//  [8]    lb

__device__ __forceinline__ void compute_row(
    float q0, float q1, float qd0, float qd1, float qdd0, float qdd1,
    const W1p& w, const float* __restrict__ w2r, float gb0, float gb1,
    const float* __restrict__ tab, float& t0, float& t1)
{
    // z = W1 q + b1, packed over j-pairs (3 ffma2 instead of 12 fmaf)
    const u64 q0p = pk2(q0, q0), q1p = pk2(q1, q1);
    float z[6];
    upk2(ffma2(w.c0[0], q0p, ffma2(w.c1[0], q1p, w.bp[0])), z[0], z[1]);
    upk2(ffma2(w.c0[1], q0p, ffma2(w.c1[1], q1p, w.bp[1])), z[2], z[3]);
    upk2(ffma2(w.c0[2], q0p, ffma2(w.c1[2], q1p, w.bp[2])), z[4], z[5]);

    // h = relu(z); g accumulates (scalar — packing is issue-neutral here);
    // mask from sign bits
    int mask = 0;
    float g0 = gb0, g1 = gb1;
#pragma unroll
    for (int j = 0; j < 6; j++) {
        mask |= (int)((~__float_as_uint(z[j])) >> 31) << j;
        float h = fmaxf(z[j], 0.0f);
        g0 = fmaf(w2r[j],     h, g0);
        g1 = fmaf(w2r[6 + j], h, g1);
    }

    // 9 scalar LDS at odd stride (<=2-way conflicts)
    const float* e = tab + mask * TS;
    const float S00 = e[0], S01 = e[1], S10 = e[2], S11 = e[3];
    const float s30 = fmaf(S00, q0, fmaf(S01, q1, e[4]));
    const float s31 = fmaf(S10, q0, fmaf(S11, q1, e[5]));
    const float E0 = e[6], E1 = e[7];
    const float c = fmaf(E0, q0, fmaf(E1, q1, e[8]));   // lo

    const float a = fmaxf(s30, 0.0f);
    const float b = fmaxf(s31, 0.0f);

    // masked Jacobian via select (FSEL), no mul
    const float d00 = (s30 > 0.0f) ? S00 : 0.0f;
    const float d01 = (s30 > 0.0f) ? S01 : 0.0f;
    const float d10 = (s31 > 0.0f) ? S10 : 0.0f;
    const float d11 = (s31 > 0.0f) ? S11 : 0.0f;

    // time derivatives
    const float da = fmaf(d00, qd0, d01 * qd1);
    const float db = fmaf(d10, qd0, d11 * qd1);
    const float dc = fmaf(E0,  qd0, E1  * qd1);

    // H q_ddot = L^T (L q_ddot) + eps q_ddot,  L = [[a,0],[c,b]]
    const float Lq0 = a * qdd0;
    const float Lq1 = fmaf(c, qdd0, b * qdd1);
    const float Hq0 = fmaf(a, Lq0, fmaf(c, Lq1, EPS * qdd0));
    const float Hq1 = fmaf(b, Lq1, EPS * qdd1);

    // dH_dt terms
    const float dh01 = fmaf(a, dc, c * da);
    const float dHq0 = fmaf(2.0f * a * da, qd0, dh01 * qd1);
    const float dHq1 = fmaf(dh01, qd0, 2.0f * fmaf(c, dc, b * db) * qd1);

    // quad via shared factors: quad_i = d0i*P0 + E_i*P1 + d1i*P2
    const float Ltq0 = fmaf(a, qd0, c * qd1);
    const float Ltq1 = b * qd1;
    const float tw0 = Ltq0 + Ltq0;
    const float tw1 = Ltq1 + Ltq1;
    const float P0 = tw0 * qd0;
    const float P1 = tw0 * qd1;
    const float P2 = tw1 * qd1;

    const float base0 = Hq0 + dHq0 + g0;
    const float base1 = Hq1 + dHq1 + g1;
    t0 = fmaf(d00, P0, fmaf(E0, P1, fmaf(d10, P2, base0)));
    t1 = fmaf(d01, P0, fmaf(E1, P1, fmaf(d11, P2, base1)));
}

__global__ void __launch_bounds__(128, 7)
lnn_tau_kernel(const float* __restrict__ x,
               const float* __restrict__ W1, const float* __restrict__ b1,
               const float* __restrict__ W2, const float* __restrict__ b2,
               const float* __restrict__ W3, const float* __restrict__ b3,
               const float* __restrict__ W4, const float* __restrict__ b4,
               float* __restrict__ out, int n)
{
    __shared__ float tab[64 * TS];

    // Build the 64-entry mask table (S, sb, E, lb).
    if (threadIdx.x < 64) {
        const int m = threadIdx.x;
        float S00 = 0.f, S01 = 0.f, S10 = 0.f, S11 = 0.f;
        float sb0 = b3[0], sb1 = b3[1];
        float E0 = 0.f, E1 = 0.f, lb = b4[0];
#pragma unroll
        for (int j = 0; j < 6; j++) {
            if ((m >> j) & 1) {
                const float a0 = W1[2 * j], a1 = W1[2 * j + 1], bb = b1[j];
                const float w30 = W3[j], w31 = W3[6 + j], w4j = W4[j];
                S00 = fmaf(w30, a0, S00); S01 = fmaf(w30, a1, S01); sb0 = fmaf(w30, bb, sb0);
                S10 = fmaf(w31, a0, S10); S11 = fmaf(w31, a1, S11); sb1 = fmaf(w31, bb, sb1);
                E0  = fmaf(w4j, a0, E0);  E1  = fmaf(w4j, a1, E1);  lb  = fmaf(w4j, bb, lb);
            }
        }
        float* e = tab + m * TS;
        e[0] = S00; e[1] = S01; e[2] = S10; e[3] = S11;
        e[4] = sb0; e[5] = sb1;
        e[6] = E0;  e[7] = E1;  e[8] = lb;
    }

    // Per-thread weight registers, loaded ONCE, amortized over ~8 iterations.
    W1p w;
#pragma unroll
    for (int p = 0; p < 3; p++) {
        w.c0[p] = pk2(__ldg(W1 + 4 * p),     __ldg(W1 + 4 * p + 2));
        w.c1[p] = pk2(__ldg(W1 + 4 * p + 1), __ldg(W1 + 4 * p + 3));
        w.bp[p] = pk2(__ldg(b1 + 2 * p),     __ldg(b1 + 2 * p + 1));
    }
    float w2r[12];
#pragma unroll
    for (int j = 0; j < 6; j++) {
        w2r[j]     = __ldg(W2 + j);
        w2r[6 + j] = __ldg(W2 + 6 + j);
    }
    const float gb0 = __ldg(b2 + 0);
    const float gb1 = __ldg(b2 + 1);
    __syncthreads();

    const int np = n >> 1;  // pairs of rows
    const int stride = gridDim.x * blockDim.x;

    for (int p = blockIdx.x * blockDim.x + threadIdx.x; p < np; p += stride) {
        const float4* xp = reinterpret_cast<const float4*>(x + (size_t)p * 12);
        const float4 u0 = xp[0], u1 = xp[1], u2 = xp[2];

        float o0, o1, o2, o3;
        compute_row(u0.x, u0.y, u0.z, u0.w, u1.x, u1.y,
                    w, w2r, gb0, gb1, tab, o0, o1);
        compute_row(u1.z, u1.w, u2.x, u2.y, u2.z, u2.w,
                    w, w2r, gb0, gb1, tab, o2, o3);

        reinterpret_cast<float4*>(out)[p] = make_float4(o0, o1, o2, o3);
    }

    // Tail (n odd) — n is even here; kept for safety.
    if ((n & 1) && blockIdx.x == 0 && threadIdx.x == 0) {
        const int row = n - 1;
        float t0, t1;
        compute_row(x[(size_t)row * 6 + 0], x[(size_t)row * 6 + 1],
                    x[(size_t)row * 6 + 2], x[(size_t)row * 6 + 3],
                    x[(size_t)row * 6 + 4], x[(size_t)row * 6 + 5],
                    w, w2r, gb0, gb1, tab, t0, t1);
        out[(size_t)row * 2 + 0] = t0;
        out[(size_t)row * 2 + 1] = t1;
    }
}

extern "C" void kernel_launch(void* const* d_in, const int* in_sizes, int n_in,
                              void* d_out, int out_size)
{
    const float* x  = (const float*)d_in[0];
    const float* W1 = (const float*)d_in[1];
    const float* b1 = (const float*)d_in[2];
    const float* W2 = (const float*)d_in[3];
    const float* b2 = (const float*)d_in[4];
    const float* W3 = (const float*)d_in[5];
    const float* b3 = (const float*)d_in[6];
    const float* W4 = (const float*)d_in[7];
    const float* b4 = (const float*)d_in[8];
    float* out = (float*)d_out;

    const int n = in_sizes[0] / 6;   // rows

    // Persistent-style grid: 7 blocks/SM resident, grid-stride (~8 iters/thread)
    const int threads = 128;
    const int blocks = 148 * 7;
    lnn_tau_kernel<<<blocks, threads>>>(x, W1, b1, W2, b2, W3, b3, W4, b4, out, n);
}